// round 8
// baseline (speedup 1.0000x reference)
#include <cuda_runtime.h>
#include <cstdint>

// Problem constants
#define Bsz 32
#define Tlen 1024
#define Idim 512
#define Hdim 512

// Scratch for the input projection (device global: no allocation allowed)
__device__ float g_xproj[(size_t)Bsz * Tlen * Hdim];  // 64 MB

// ---------------------------------------------------------------------------
// packed f32x2 helpers (FFMA2 — ptxas never auto-fuses; PTX-only)
// ---------------------------------------------------------------------------
using u64 = unsigned long long;
__device__ __forceinline__ u64 pk2(float lo, float hi) {
    u64 r; asm("mov.b64 %0,{%1,%2};" : "=l"(r) : "f"(lo), "f"(hi)); return r;
}
__device__ __forceinline__ float2 upk2(u64 v) {
    float2 f; asm("mov.b64 {%0,%1},%2;" : "=f"(f.x), "=f"(f.y) : "l"(v)); return f;
}
__device__ __forceinline__ u64 fma2(u64 a, u64 b, u64 c) {
    u64 d; asm("fma.rn.f32x2 %0,%1,%2,%3;" : "=l"(d) : "l"(a), "l"(b), "l"(c)); return d;
}
__device__ __forceinline__ u64 add2(u64 a, u64 b) {
    u64 d; asm("add.rn.f32x2 %0,%1,%2;" : "=l"(d) : "l"(a), "l"(b)); return d;
}
__device__ __forceinline__ u64 mul2(u64 a, u64 b) {
    u64 d; asm("mul.rn.f32x2 %0,%1,%2;" : "=l"(d) : "l"(a), "l"(b)); return d;
}

__device__ __forceinline__ uint32_t s2u(const void* p) {
    uint32_t a;
    asm("{ .reg .u64 t; cvta.to.shared.u64 t, %1; cvt.u32.u64 %0, t; }"
        : "=r"(a) : "l"(p));
    return a;
}
__device__ __forceinline__ uint32_t mapa_rank(uint32_t laddr, uint32_t rank) {
    uint32_t r;
    asm("mapa.shared::cluster.u32 %0, %1, %2;" : "=r"(r) : "r"(laddr), "r"(rank));
    return r;
}
__device__ __forceinline__ void mbar_init(uint32_t mb, uint32_t cnt) {
    asm volatile("mbarrier.init.shared.b64 [%0], %1;" :: "r"(mb), "r"(cnt) : "memory");
}
__device__ __forceinline__ void st_cluster_u64(uint32_t addr, u64 v) {
    asm volatile("st.shared::cluster.b64 [%0], %1;" :: "r"(addr), "l"(v) : "memory");
}
__device__ __forceinline__ void mbar_arrive_release_addr(uint32_t addr) {
    asm volatile("mbarrier.arrive.release.cluster.shared::cluster.b64 _, [%0];"
                 :: "r"(addr) : "memory");
}
__device__ __forceinline__ void mbar_wait_parity(uint32_t mb, uint32_t parity) {
    asm volatile(
        "{\n\t"
        ".reg .pred P;\n\t"
        "WLOOP_%=:\n\t"
        "mbarrier.try_wait.parity.acquire.cta.shared::cta.b64 P, [%0], %1, 0x989680;\n\t"
        "@P bra.uni WDONE_%=;\n\t"
        "bra.uni WLOOP_%=;\n\t"
        "WDONE_%=:\n\t"
        "}"
        :: "r"(mb), "r"(parity) : "memory");
}
__device__ __forceinline__ void cluster_sync_asm() {
    asm volatile("barrier.cluster.arrive.aligned;" ::: "memory");
    asm volatile("barrier.cluster.wait.aligned;" ::: "memory");
}
__device__ __forceinline__ u64 shflx2(u64 v, int m) {
    float2 f = upk2(v);
    f.x = __shfl_xor_sync(0xFFFFFFFFu, f.x, m);
    f.y = __shfl_xor_sync(0xFFFFFFFFu, f.y, m);
    return pk2(f.x, f.y);
}
// Fast branch-free tanh (rel err ~1e-6, fine vs 1e-3 tolerance)
__device__ __forceinline__ float ftanh(float x) {
    float ax = fabsf(x);
    float e = __expf(-2.0f * ax);
    float r = __fdividef(1.0f - e, 1.0f + e);
    return copysignf(r, x);
}

// ---------------------------------------------------------------------------
// Kernel 1: xproj[m, h] = sum_i X[m, i] * Wih[h, i] + bih[h] + bhh[h]
//   fp32 SGEMM 128x128x16, 8x8 micro-tile, inner loop in fma.rn.f32x2
// ---------------------------------------------------------------------------
__global__ void __launch_bounds__(256) xproj_kernel(
    const float* __restrict__ X,     // [32768, 512]
    const float* __restrict__ Wih,   // [512, 512]
    const float* __restrict__ bih,
    const float* __restrict__ bhh)
{
    const int BM = 128, BN = 128, BK = 16;
    __shared__ __align__(16) float As[BK][BM + 4];
    __shared__ __align__(16) float Bs[BK][BN + 4];

    const int tid = threadIdx.x;
    const int m0 = blockIdx.y * BM;
    const int n0 = blockIdx.x * BN;
    const int tx = tid & 15;
    const int ty = tid >> 4;

    u64 acc2[8][4];
#pragma unroll
    for (int i = 0; i < 8; ++i)
#pragma unroll
        for (int j = 0; j < 4; ++j) acc2[i][j] = 0ull;

    for (int k0 = 0; k0 < Idim; k0 += BK) {
#pragma unroll
        for (int q = 0; q < 2; ++q) {
            int lin = tid + 256 * q;
            int m = lin >> 2;
            int kv = (lin & 3) << 2;
            float4 va = *(const float4*)(X + (size_t)(m0 + m) * Idim + k0 + kv);
            As[kv + 0][m] = va.x; As[kv + 1][m] = va.y;
            As[kv + 2][m] = va.z; As[kv + 3][m] = va.w;
            float4 vb = *(const float4*)(Wih + (size_t)(n0 + m) * Idim + k0 + kv);
            Bs[kv + 0][m] = vb.x; Bs[kv + 1][m] = vb.y;
            Bs[kv + 2][m] = vb.z; Bs[kv + 3][m] = vb.w;
        }
        __syncthreads();

#pragma unroll
        for (int kk = 0; kk < BK; ++kk) {
            float ra[8];
            *(float4*)&ra[0] = *(const float4*)&As[kk][ty * 8];
            *(float4*)&ra[4] = *(const float4*)&As[kk][ty * 8 + 4];
            ulonglong2 rbA = *(const ulonglong2*)&Bs[kk][tx * 8];
            ulonglong2 rbB = *(const ulonglong2*)&Bs[kk][tx * 8 + 4];
            u64 rb2[4] = { rbA.x, rbA.y, rbB.x, rbB.y };
#pragma unroll
            for (int i = 0; i < 8; ++i) {
                u64 rap = pk2(ra[i], ra[i]);
#pragma unroll
                for (int j = 0; j < 4; ++j)
                    acc2[i][j] = fma2(rap, rb2[j], acc2[i][j]);
            }
        }
        __syncthreads();
    }

    u64 bs2[4];
#pragma unroll
    for (int j = 0; j < 4; ++j) {
        float blo = bih[n0 + tx * 8 + 2 * j] + bhh[n0 + tx * 8 + 2 * j];
        float bhi = bih[n0 + tx * 8 + 2 * j + 1] + bhh[n0 + tx * 8 + 2 * j + 1];
        bs2[j] = pk2(blo, bhi);
    }

#pragma unroll
    for (int i = 0; i < 8; ++i) {
        float2 p0 = upk2(add2(acc2[i][0], bs2[0]));
        float2 p1 = upk2(add2(acc2[i][1], bs2[1]));
        float2 p2 = upk2(add2(acc2[i][2], bs2[2]));
        float2 p3 = upk2(add2(acc2[i][3], bs2[3]));
        float* crow = g_xproj + (size_t)(m0 + ty * 8 + i) * Hdim + n0 + tx * 8;
        *(float4*)(crow)     = make_float4(p0.x, p0.y, p1.x, p1.y);
        *(float4*)(crow + 4) = make_float4(p2.x, p2.y, p3.x, p3.y);
    }
}

// ---------------------------------------------------------------------------
// Kernel 2: the recurrence — all-to-all of M-partials (round-6 structure),
//   exchange via DIRECT remote stores instead of the bulk-copy engine:
//   each warp streams its 128B chunk to peer w with 2x st.shared::cluster.b64
//   per lane as soon as its GEMV finishes, then ONE
//   mbarrier.arrive.release.cluster. Count-7 barriers auto-rearm (no
//   expect_tx, no tid-0 serialization, no fence, no staging buffer).
//   xproj staging moved BEFORE the wait so its hiccup overlaps the fabric gap.
// ---------------------------------------------------------------------------
__global__ void __launch_bounds__(256, 1) __cluster_dims__(8, 1, 1)
rnn_kernel(const float* __restrict__ Whh,   // [512, 512]
           const float* __restrict__ kern,  // [4]
           float* __restrict__ out_states,  // [B, T, H]
           float* __restrict__ out_last)    // [B, H]
{
    __shared__ __align__(16) float arr[2][8][128];   // 8KB [slot][src][swz 512B]
    __shared__ __align__(16) float hloc[2][64];      // h_t[own rows], batch-major
    __shared__ __align__(16) float xs[2][2][8][64];  // 8KB xproj stage
    __shared__ __align__(16) float xout[2][8][64];   // 4KB output stage
    __shared__ __align__(8)  u64 mbars[2];

    const int tid   = threadIdx.x;
    const int lane  = tid & 31;
    const int w     = tid >> 5;            // warp id == destination peer
    const int slice = blockIdx.x;          // cluster rank 0..7
    const int grp   = blockIdx.y;          // 0..15
    const int b0    = grp * 2;

    // Register weights: rows 64w+2*lane, +1 of Whh, columns [64*slice, +64),
    // packed along K (pairs of adjacent columns).
    u64 wR0[32], wR1[32];
    {
        const float* r0p = Whh + (size_t)(64 * w + 2 * lane) * Hdim + 64 * slice;
        const float* r1p = r0p + Hdim;
#pragma unroll
        for (int m = 0; m < 16; ++m) {
            ulonglong2 u0 = *(const ulonglong2*)(r0p + 4 * m);
            ulonglong2 u1 = *(const ulonglong2*)(r1p + 4 * m);
            wR0[2 * m] = u0.x; wR0[2 * m + 1] = u0.y;
            wR1[2 * m] = u1.x; wR1[2 * m + 1] = u1.y;
        }
    }
    const u64 kk0 = pk2(kern[0], kern[0]), kk1 = pk2(kern[1], kern[1]);
    const u64 kk2 = pk2(kern[2], kern[2]), kk3 = pk2(kern[3], kern[3]);

    // Init count-7 barriers (7 sending warps per peer; auto-rearm per phase)
    const uint32_t mb0 = s2u(&mbars[0]);
    if (tid == 0) {
        mbar_init(mb0, 7);
        mbar_init(mb0 + 8, 7);
    }

    // Per-warp remote targets on peer w (this CTA's src block, own swizzle)
    const uint32_t arr_b = s2u(arr);
    const uint32_t rdst  = mapa_rank(arr_b, w)
                         + (uint32_t)(slice * 512 + ((lane + 5 * slice) & 31) * 16);
    const uint32_t rbar  = mapa_rank(mb0, w);

    cluster_sync_asm();   // barrier init visible cluster-wide

    // xproj staging: one float4 per thread per 8-step group
    const int pb  = tid >> 7;
    const int pt  = (tid >> 4) & 7;
    const int pu  = tid & 15;
    const float* xsrc = g_xproj + (size_t)(b0 + pb) * Tlen * Hdim
                        + (size_t)pt * Hdim + slice * 64 + pu * 4;
    *(float4*)&xs[0][pb][pt][pu * 4] = *(const float4*)(xsrc);        // group 0
    float4 xpre = *(const float4*)(xsrc + 8 * Hdim);                  // group 1
    __syncthreads();

    // Phase-A roles: thread -> (row, quad); quad handles source pair 2q,2q+1
    const int row  = tid >> 2;     // 0..63 (own-row index)
    const int quad = tid & 3;

    // Register M-ring: M_{t-2}, M_{t-3}, M_{t-4} for this row, packed (b0,b1)
    u64 ring0 = 0ull, ring1 = 0ull, ring2 = 0ull;

    const char* arrc = (const char*)arr;

    for (int t = 0; t < Tlen; ++t) {
        // Stage next xproj group BEFORE the wait (overlaps the fabric gap)
        if ((t & 7) == 0) {
            int g = t >> 3;
            *(float4*)&xs[(g + 1) & 1][pb][pt][pu * 4] = xpre;
            if (t + 16 < Tlen)
                xpre = *(const float4*)(xsrc + (size_t)(t + 16) * Hdim);
        }

        // ---- Phase A: wait, gather M_{t-1}, taps, tanh -> h_t (own rows) ----
        u64 Mt1 = 0ull;
        if (t > 0) {
            mbar_wait_parity(mb0 + ((t - 1) & 1) * 8, ((t - 1) >> 1) & 1);

            const char* ab = arrc + ((t - 1) & 1) * 4096;
            const int s0 = 2 * quad, s1 = 2 * quad + 1;
            const int pbk = row >> 1, rb = (row & 1) * 8;
            u64 v0 = *(const u64*)(ab + s0 * 512 + (((pbk + 5 * s0) & 31) * 16 + rb));
            u64 v1 = *(const u64*)(ab + s1 * 512 + (((pbk + 5 * s1) & 31) * 16 + rb));
            u64 m = add2(v0, v1);
            m = add2(m, shflx2(m, 1));
            m = add2(m, shflx2(m, 2));
            Mt1 = m;                       // all 4 quad lanes hold full M[row]
        }

        // 4-tap Lagrange on the register M-ring
        u64 rr = fma2(kk0, Mt1, fma2(kk1, ring0, fma2(kk2, ring1, mul2(kk3, ring2))));
        ring2 = ring1; ring1 = ring0; ring0 = Mt1;

        if (quad < 2) {                    // quad == batch
            float2 rf = upk2(rr);
            float pre = (quad == 0) ? rf.x : rf.y;
            float val = ftanh(pre + xs[(t >> 3) & 1][quad][t & 7][row]);
            hloc[quad][row] = val;
            xout[quad][t & 7][row] = val;
            if (t == Tlen - 1)
                out_last[(size_t)(b0 + quad) * Hdim + slice * 64 + row] = val;
        }

        __syncthreads();   // hloc/xout ready

        // ---- Phase B: per-warp partial chunk GEMV + direct remote stores ----
        if (t < Tlen - 1) {
            u64 aA0 = 0ull, cA0 = 0ull, aA1 = 0ull, cA1 = 0ull;
            u64 aB0 = 0ull, cB0 = 0ull, aB1 = 0ull, cB1 = 0ull;
#pragma unroll
            for (int m = 0; m < 16; ++m) {
                ulonglong2 h0 = *(const ulonglong2*)&hloc[0][4 * m];
                ulonglong2 h1 = *(const ulonglong2*)&hloc[1][4 * m];
                aA0 = fma2(wR0[2 * m],     h0.x, aA0);
                cA0 = fma2(wR0[2 * m + 1], h0.y, cA0);
                aA1 = fma2(wR0[2 * m],     h1.x, aA1);
                cA1 = fma2(wR0[2 * m + 1], h1.y, cA1);
                aB0 = fma2(wR1[2 * m],     h0.x, aB0);
                cB0 = fma2(wR1[2 * m + 1], h0.y, cB0);
                aB1 = fma2(wR1[2 * m],     h1.x, aB1);
                cB1 = fma2(wR1[2 * m + 1], h1.y, cB1);
            }
            float2 fA0 = upk2(add2(aA0, cA0));
            float2 fA1 = upk2(add2(aA1, cA1));
            float2 fB0 = upk2(add2(aB0, cB0));
            float2 fB1 = upk2(add2(aB1, cB1));
            // rows 2*lane, 2*lane+1 of chunk w; (r0b0,r0b1) , (r1b0,r1b1)
            u64 oA = pk2(fA0.x + fA0.y, fA1.x + fA1.y);
            u64 oB = pk2(fB0.x + fB0.y, fB1.x + fB1.y);

            if (w == slice) {
                // own chunk: local STS, covered by end-of-step syncthreads
                float* dstp = &arr[t & 1][slice][((lane + 5 * slice) & 31) * 4];
                *(u64*)(dstp)     = oA;
                *(u64*)(dstp + 2) = oB;
            } else {
                const uint32_t a = rdst + (uint32_t)((t & 1) * 4096);
                st_cluster_u64(a,     oA);
                st_cluster_u64(a + 8, oB);
                __syncwarp();
                if (lane == 0)
                    mbar_arrive_release_addr(rbar + (uint32_t)((t & 1) * 8));
            }
        }

        // Flush buffered outputs (off the critical path)
        if ((t & 7) == 7) {
            int t0 = t - 7;
            *(float4*)(out_states + (size_t)(b0 + pb) * Tlen * Hdim
                       + (size_t)(t0 + pt) * Hdim + slice * 64 + pu * 4)
                = *(const float4*)&xout[pb][pt][pu * 4];
        }

        __syncthreads();   // own-chunk STS + xout ordering for next step
    }

    // No CTA may exit while peers' remote stores could still target it
    cluster_sync_asm();
}

// ---------------------------------------------------------------------------
extern "C" void kernel_launch(void* const* d_in, const int* in_sizes, int n_in,
                              void* d_out, int out_size)
{
    (void)in_sizes; (void)n_in; (void)out_size;
    const float* x    = (const float*)d_in[0];   // [32, 1024, 512]
    const float* Wih  = (const float*)d_in[1];   // [512, 512]
    const float* Whh  = (const float*)d_in[2];   // [512, 512]
    const float* bih  = (const float*)d_in[3];   // [512]
    const float* bhh  = (const float*)d_in[4];   // [512]
    const float* kern = (const float*)d_in[5];   // [4]

    float* out        = (float*)d_out;
    float* out_states = out;                                   // [32,1024,512]
    float* out_last   = out + (size_t)Bsz * Tlen * Hdim;       // [32,512]

    dim3 gg(Hdim / 128, (Bsz * Tlen) / 128);   // (4, 256)
    xproj_kernel<<<gg, 256>>>(x, Wih, bih, bhh);

    dim3 gr(8, 16);
    rnn_kernel<<<gr, 256>>>(Whh, kern, out_states, out_last);
}

// round 9
// speedup vs baseline: 1.7087x; 1.7087x over previous
#include <cuda_runtime.h>
#include <cstdint>

// Problem constants
#define Bsz 32
#define Tlen 1024
#define Idim 512
#define Hdim 512

// Scratch for the input projection (device global: no allocation allowed)
__device__ float g_xproj[(size_t)Bsz * Tlen * Hdim];  // 64 MB

// ---------------------------------------------------------------------------
// packed f32x2 helpers (FFMA2 — ptxas never auto-fuses; PTX-only)
// ---------------------------------------------------------------------------
using u64 = unsigned long long;
__device__ __forceinline__ u64 pk2(float lo, float hi) {
    u64 r; asm("mov.b64 %0,{%1,%2};" : "=l"(r) : "f"(lo), "f"(hi)); return r;
}
__device__ __forceinline__ float2 upk2(u64 v) {
    float2 f; asm("mov.b64 {%0,%1},%2;" : "=f"(f.x), "=f"(f.y) : "l"(v)); return f;
}
__device__ __forceinline__ u64 fma2(u64 a, u64 b, u64 c) {
    u64 d; asm("fma.rn.f32x2 %0,%1,%2,%3;" : "=l"(d) : "l"(a), "l"(b), "l"(c)); return d;
}
__device__ __forceinline__ u64 add2(u64 a, u64 b) {
    u64 d; asm("add.rn.f32x2 %0,%1,%2;" : "=l"(d) : "l"(a), "l"(b)); return d;
}
__device__ __forceinline__ u64 mul2(u64 a, u64 b) {
    u64 d; asm("mul.rn.f32x2 %0,%1,%2;" : "=l"(d) : "l"(a), "l"(b)); return d;
}

__device__ __forceinline__ uint32_t s2u(const void* p) {
    uint32_t a;
    asm("{ .reg .u64 t; cvta.to.shared.u64 t, %1; cvt.u32.u64 %0, t; }"
        : "=r"(a) : "l"(p));
    return a;
}
__device__ __forceinline__ uint32_t mapa_rank(uint32_t laddr, uint32_t rank) {
    uint32_t r;
    asm("mapa.shared::cluster.u32 %0, %1, %2;" : "=r"(r) : "r"(laddr), "r"(rank));
    return r;
}
__device__ __forceinline__ void mbar_init(uint32_t mb, uint32_t cnt) {
    asm volatile("mbarrier.init.shared.b64 [%0], %1;" :: "r"(mb), "r"(cnt) : "memory");
}
__device__ __forceinline__ void mbar_arrive_expect_tx(uint32_t mb, uint32_t bytes) {
    asm volatile("mbarrier.arrive.expect_tx.shared.b64 _, [%0], %1;"
                 :: "r"(mb), "r"(bytes) : "memory");
}
__device__ __forceinline__ void mbar_wait_parity(uint32_t mb, uint32_t parity) {
    asm volatile(
        "{\n\t"
        ".reg .pred P;\n\t"
        "WLOOP_%=:\n\t"
        "mbarrier.try_wait.parity.acquire.cta.shared::cta.b64 P, [%0], %1, 0x989680;\n\t"
        "@P bra.uni WDONE_%=;\n\t"
        "bra.uni WLOOP_%=;\n\t"
        "WDONE_%=:\n\t"
        "}"
        :: "r"(mb), "r"(parity) : "memory");
}
__device__ __forceinline__ void bulk_dsmem(uint32_t dst, uint32_t src,
                                           uint32_t bytes, uint32_t rembar) {
    asm volatile(
        "cp.async.bulk.shared::cluster.shared::cta.mbarrier::complete_tx::bytes "
        "[%0], [%1], %2, [%3];"
        :: "r"(dst), "r"(src), "r"(bytes), "r"(rembar) : "memory");
}
__device__ __forceinline__ void fence_proxy_async_cta() {
    asm volatile("fence.proxy.async.shared::cta;" ::: "memory");
}
__device__ __forceinline__ void cluster_sync_asm() {
    asm volatile("barrier.cluster.arrive.aligned;" ::: "memory");
    asm volatile("barrier.cluster.wait.aligned;" ::: "memory");
}
__device__ __forceinline__ u64 shflx2(u64 v, int m) {
    float2 f = upk2(v);
    f.x = __shfl_xor_sync(0xFFFFFFFFu, f.x, m);
    f.y = __shfl_xor_sync(0xFFFFFFFFu, f.y, m);
    return pk2(f.x, f.y);
}
// Fast branch-free tanh (rel err ~1e-6, fine vs 1e-3 tolerance)
__device__ __forceinline__ float ftanh(float x) {
    float ax = fabsf(x);
    float e = __expf(-2.0f * ax);
    float r = __fdividef(1.0f - e, 1.0f + e);
    return copysignf(r, x);
}

// ---------------------------------------------------------------------------
// Kernel 1: xproj[m, h] = sum_i X[m, i] * Wih[h, i] + bih[h] + bhh[h]
//   fp32 SGEMM 128x128x16, 8x8 micro-tile, inner loop in fma.rn.f32x2
// ---------------------------------------------------------------------------
__global__ void __launch_bounds__(256) xproj_kernel(
    const float* __restrict__ X,     // [32768, 512]
    const float* __restrict__ Wih,   // [512, 512]
    const float* __restrict__ bih,
    const float* __restrict__ bhh)
{
    const int BM = 128, BN = 128, BK = 16;
    __shared__ __align__(16) float As[BK][BM + 4];
    __shared__ __align__(16) float Bs[BK][BN + 4];

    const int tid = threadIdx.x;
    const int m0 = blockIdx.y * BM;
    const int n0 = blockIdx.x * BN;
    const int tx = tid & 15;
    const int ty = tid >> 4;

    u64 acc2[8][4];
#pragma unroll
    for (int i = 0; i < 8; ++i)
#pragma unroll
        for (int j = 0; j < 4; ++j) acc2[i][j] = 0ull;

    for (int k0 = 0; k0 < Idim; k0 += BK) {
#pragma unroll
        for (int q = 0; q < 2; ++q) {
            int lin = tid + 256 * q;
            int m = lin >> 2;
            int kv = (lin & 3) << 2;
            float4 va = *(const float4*)(X + (size_t)(m0 + m) * Idim + k0 + kv);
            As[kv + 0][m] = va.x; As[kv + 1][m] = va.y;
            As[kv + 2][m] = va.z; As[kv + 3][m] = va.w;
            float4 vb = *(const float4*)(Wih + (size_t)(n0 + m) * Idim + k0 + kv);
            Bs[kv + 0][m] = vb.x; Bs[kv + 1][m] = vb.y;
            Bs[kv + 2][m] = vb.z; Bs[kv + 3][m] = vb.w;
        }
        __syncthreads();

#pragma unroll
        for (int kk = 0; kk < BK; ++kk) {
            float ra[8];
            *(float4*)&ra[0] = *(const float4*)&As[kk][ty * 8];
            *(float4*)&ra[4] = *(const float4*)&As[kk][ty * 8 + 4];
            ulonglong2 rbA = *(const ulonglong2*)&Bs[kk][tx * 8];
            ulonglong2 rbB = *(const ulonglong2*)&Bs[kk][tx * 8 + 4];
            u64 rb2[4] = { rbA.x, rbA.y, rbB.x, rbB.y };
#pragma unroll
            for (int i = 0; i < 8; ++i) {
                u64 rap = pk2(ra[i], ra[i]);
#pragma unroll
                for (int j = 0; j < 4; ++j)
                    acc2[i][j] = fma2(rap, rb2[j], acc2[i][j]);
            }
        }
        __syncthreads();
    }

    u64 bs2[4];
#pragma unroll
    for (int j = 0; j < 4; ++j) {
        float blo = bih[n0 + tx * 8 + 2 * j] + bhh[n0 + tx * 8 + 2 * j];
        float bhi = bih[n0 + tx * 8 + 2 * j + 1] + bhh[n0 + tx * 8 + 2 * j + 1];
        bs2[j] = pk2(blo, bhi);
    }

#pragma unroll
    for (int i = 0; i < 8; ++i) {
        float2 p0 = upk2(add2(acc2[i][0], bs2[0]));
        float2 p1 = upk2(add2(acc2[i][1], bs2[1]));
        float2 p2 = upk2(add2(acc2[i][2], bs2[2]));
        float2 p3 = upk2(add2(acc2[i][3], bs2[3]));
        float* crow = g_xproj + (size_t)(m0 + ty * 8 + i) * Hdim + n0 + tx * 8;
        *(float4*)(crow)     = make_float4(p0.x, p0.y, p1.x, p1.y);
        *(float4*)(crow + 4) = make_float4(p2.x, p2.y, p3.x, p3.y);
    }
}

// ---------------------------------------------------------------------------
// Kernel 2: the recurrence — all-to-all of M-partials via bulk DSMEM engine
//   (the round-6 structure, which is the measured best). Two gap-filler
//   changes only: (1) xproj staging happens BEFORE the wait, so its LDG/STS
//   hiccup overlaps the fabric gap; (2) xout is double-buffered and the
//   global flush also happens BEFORE the wait (previous group), off the
//   critical path. Exchange protocol byte-identical to round 6.
// ---------------------------------------------------------------------------
__global__ void __launch_bounds__(256, 1) __cluster_dims__(8, 1, 1)
rnn_kernel(const float* __restrict__ Whh,   // [512, 512]
           const float* __restrict__ kern,  // [4]
           float* __restrict__ out_states,  // [B, T, H]
           float* __restrict__ out_last)    // [B, H]
{
    __shared__ __align__(16) float arr[2][8][128];    // 8KB [slot][src][swz 512B]
    __shared__ __align__(16) float stg[2][8][128];    // 8KB [slot][warp][512B]
    __shared__ __align__(16) float hloc[2][64];       // h_t[own rows], batch-major
    __shared__ __align__(16) float xs[2][2][8][64];   // 8KB xproj stage
    __shared__ __align__(16) float xout[2][2][8][64]; // 8KB output stage (dbuf)
    __shared__ __align__(8)  u64 mbars[2];

    const int tid   = threadIdx.x;
    const int lane  = tid & 31;
    const int w     = tid >> 5;            // warp id == destination peer
    const int slice = blockIdx.x;          // cluster rank 0..7
    const int grp   = blockIdx.y;          // 0..15
    const int b0    = grp * 2;

    // Register weights: rows 64w+2*lane, +1 of Whh, columns [64*slice, +64),
    // packed along K (pairs of adjacent columns).
    u64 wR0[32], wR1[32];
    {
        const float* r0p = Whh + (size_t)(64 * w + 2 * lane) * Hdim + 64 * slice;
        const float* r1p = r0p + Hdim;
#pragma unroll
        for (int m = 0; m < 16; ++m) {
            ulonglong2 u0 = *(const ulonglong2*)(r0p + 4 * m);
            ulonglong2 u1 = *(const ulonglong2*)(r1p + 4 * m);
            wR0[2 * m] = u0.x; wR0[2 * m + 1] = u0.y;
            wR1[2 * m] = u1.x; wR1[2 * m + 1] = u1.y;
        }
    }
    const u64 kk0 = pk2(kern[0], kern[0]), kk1 = pk2(kern[1], kern[1]);
    const u64 kk2 = pk2(kern[2], kern[2]), kk3 = pk2(kern[3], kern[3]);

    // Init + arm tx-barriers (count 1, expect 7*512 B per slot)
    const uint32_t mb0 = s2u(&mbars[0]);
    if (tid == 0) {
        mbar_init(mb0, 1);
        mbar_init(mb0 + 8, 1);
        mbar_arrive_expect_tx(mb0, 7 * 512);
        mbar_arrive_expect_tx(mb0 + 8, 7 * 512);
    }

    // Per-warp remote targets (peer w): its arr slot at src index = MY slice
    const uint32_t arr_b = s2u(arr);
    const uint32_t dst_b = mapa_rank(arr_b, w) + (uint32_t)(slice * 512);
    const uint32_t bar_b = mapa_rank(mb0, w);

    cluster_sync_asm();   // barrier init visible cluster-wide

    // xproj staging: one float4 per thread per 8-step group
    const int pb  = tid >> 7;
    const int pt  = (tid >> 4) & 7;
    const int pu  = tid & 15;
    const float* xsrc = g_xproj + (size_t)(b0 + pb) * Tlen * Hdim
                        + (size_t)pt * Hdim + slice * 64 + pu * 4;
    *(float4*)&xs[0][pb][pt][pu * 4] = *(const float4*)(xsrc);        // group 0
    float4 xpre = *(const float4*)(xsrc + 8 * Hdim);                  // group 1
    __syncthreads();

    // Phase-A roles: thread -> (row, quad); quad handles source pair 2q,2q+1
    const int row  = tid >> 2;     // 0..63 (own-row index)
    const int quad = tid & 3;

    // Register M-ring: M_{t-2}, M_{t-3}, M_{t-4} for this row, packed (b0,b1)
    u64 ring0 = 0ull, ring1 = 0ull, ring2 = 0ull;

    const char* arrc = (const char*)arr;

    for (int t = 0; t < Tlen; ++t) {
        // ---- Gap fillers BEFORE the wait: staging + output flush ----
        if ((t & 7) == 0) {
            int g = t >> 3;
            // Stage xproj group g+1 into the idle buffer
            *(float4*)&xs[(g + 1) & 1][pb][pt][pu * 4] = xpre;
            if (t + 16 < Tlen)
                xpre = *(const float4*)(xsrc + (size_t)(t + 16) * Hdim);
            // Flush the previous output group (written through step t-1;
            // ordered by step t-1's phase A->B syncthreads)
            if (t > 0) {
                *(float4*)(out_states + (size_t)(b0 + pb) * Tlen * Hdim
                           + (size_t)(t - 8 + pt) * Hdim + slice * 64 + pu * 4)
                    = *(const float4*)&xout[(g - 1) & 1][pb][pt][pu * 4];
            }
        }

        // ---- Phase A: wait, gather M_{t-1}, taps, tanh -> h_t (own rows) ----
        u64 Mt1 = 0ull;
        if (t > 0) {
            const uint32_t bar = mb0 + ((t - 1) & 1) * 8;
            mbar_wait_parity(bar, ((t - 1) >> 1) & 1);
            if (tid == 0)
                mbar_arrive_expect_tx(bar, 7 * 512);   // re-arm for step t+1

            const char* ab = arrc + ((t - 1) & 1) * 4096;
            const int s0 = 2 * quad, s1 = 2 * quad + 1;
            const int pbk = row >> 1, rb = (row & 1) * 8;
            u64 v0 = *(const u64*)(ab + s0 * 512 + (((pbk + 5 * s0) & 31) * 16 + rb));
            u64 v1 = *(const u64*)(ab + s1 * 512 + (((pbk + 5 * s1) & 31) * 16 + rb));
            u64 m = add2(v0, v1);
            m = add2(m, shflx2(m, 1));
            m = add2(m, shflx2(m, 2));
            Mt1 = m;                       // all 4 quad lanes hold full M[row]
        }

        // 4-tap Lagrange on the register M-ring
        u64 rr = fma2(kk0, Mt1, fma2(kk1, ring0, fma2(kk2, ring1, mul2(kk3, ring2))));
        ring2 = ring1; ring1 = ring0; ring0 = Mt1;

        if (quad < 2) {                    // quad == batch
            float2 rf = upk2(rr);
            float pre = (quad == 0) ? rf.x : rf.y;
            float val = ftanh(pre + xs[(t >> 3) & 1][quad][t & 7][row]);
            hloc[quad][row] = val;
            xout[(t >> 3) & 1][quad][t & 7][row] = val;
            if (t == Tlen - 1)
                out_last[(size_t)(b0 + quad) * Hdim + slice * 64 + row] = val;
        }

        __syncthreads();   // hloc/xout ready; xs stage ordered

        // ---- Phase B: per-warp partial chunk GEMV + immediate send ----
        if (t < Tlen - 1) {
            u64 aA0 = 0ull, cA0 = 0ull, aA1 = 0ull, cA1 = 0ull;
            u64 aB0 = 0ull, cB0 = 0ull, aB1 = 0ull, cB1 = 0ull;
#pragma unroll
            for (int m = 0; m < 16; ++m) {
                ulonglong2 h0 = *(const ulonglong2*)&hloc[0][4 * m];
                ulonglong2 h1 = *(const ulonglong2*)&hloc[1][4 * m];
                aA0 = fma2(wR0[2 * m],     h0.x, aA0);
                cA0 = fma2(wR0[2 * m + 1], h0.y, cA0);
                aA1 = fma2(wR0[2 * m],     h1.x, aA1);
                cA1 = fma2(wR0[2 * m + 1], h1.y, cA1);
                aB0 = fma2(wR1[2 * m],     h0.x, aB0);
                cB0 = fma2(wR1[2 * m + 1], h0.y, cB0);
                aB1 = fma2(wR1[2 * m],     h1.x, aB1);
                cB1 = fma2(wR1[2 * m + 1], h1.y, cB1);
            }
            float2 fA0 = upk2(add2(aA0, cA0));
            float2 fA1 = upk2(add2(aA1, cA1));
            float2 fB0 = upk2(add2(aB0, cB0));
            float2 fB1 = upk2(add2(aB1, cB1));
            // rows 2*lane, 2*lane+1 of chunk w; values (r0b0,r0b1,r1b0,r1b1)
            float4 o = make_float4(fA0.x + fA0.y, fA1.x + fA1.y,
                                   fB0.x + fB0.y, fB1.x + fB1.y);
            float* dstp = (w == slice) ? &arr[t & 1][slice][0]
                                       : &stg[t & 1][w][0];
            *(float4*)(dstp + ((lane + 5 * slice) & 31) * 4) = o;
            __syncwarp();
            if (w != slice && lane == 0) {
                fence_proxy_async_cta();
                bulk_dsmem(dst_b + (uint32_t)((t & 1) * 4096),
                           s2u(&stg[t & 1][w][0]), 512,
                           bar_b + (uint32_t)((t & 1) * 8));
            }
        }

        __syncthreads();   // own-chunk STS visible to next step's gather
    }

    // Final output group (t = 1016..1023, buffer (127)&1 = 1)
    *(float4*)(out_states + (size_t)(b0 + pb) * Tlen * Hdim
               + (size_t)(Tlen - 8 + pt) * Hdim + slice * 64 + pu * 4)
        = *(const float4*)&xout[1][pb][pt][pu * 4];

    // No CTA may exit while peers' bulk copies could still target it
    cluster_sync_asm();
}

// ---------------------------------------------------------------------------
extern "C" void kernel_launch(void* const* d_in, const int* in_sizes, int n_in,
                              void* d_out, int out_size)
{
    (void)in_sizes; (void)n_in; (void)out_size;
    const float* x    = (const float*)d_in[0];   // [32, 1024, 512]
    const float* Wih  = (const float*)d_in[1];   // [512, 512]
    const float* Whh  = (const float*)d_in[2];   // [512, 512]
    const float* bih  = (const float*)d_in[3];   // [512]
    const float* bhh  = (const float*)d_in[4];   // [512]
    const float* kern = (const float*)d_in[5];   // [4]

    float* out        = (float*)d_out;
    float* out_states = out;                                   // [32,1024,512]
    float* out_last   = out + (size_t)Bsz * Tlen * Hdim;       // [32,512]

    dim3 gg(Hdim / 128, (Bsz * Tlen) / 128);   // (4, 256)
    xproj_kernel<<<gg, 256>>>(x, Wih, bih, bhh);

    dim3 gr(8, 16);
    rnn_kernel<<<gr, 256>>>(Whh, kern, out_states, out_last);
}